// round 2
// baseline (speedup 1.0000x reference)
#include <cuda_runtime.h>
#include <cuda_bf16.h>

// N=1, C=2, H=64, W=64, D=32, radius=(3,3,1), SIGMA_XY=5, SIGMA_IMG=0.1, WEIGHT=1
#define NH 64
#define NW 64
#define ND 32
#define NL (NH * NW * ND)   // 131072
#define NBLK (NL / 256)     // 512 blocks of 256 threads

__device__ float    g_part[NBLK];
__device__ unsigned g_cnt = 0;   // arrival counter; last block resets to 0 (graph-replay safe)

__global__ __launch_bounds__(256) void k_all(const float* __restrict__ y,
                                             const float* __restrict__ s,
                                             const float* __restrict__ spacing,
                                             float* __restrict__ out) {
    const int p = blockIdx.x * 256 + threadIdx.x;
    const int d = p & (ND - 1);          // lane == d (warp = one full d-column)
    const int w = (p >> 5) & (NW - 1);
    const int h = p >> 11;

    const float sp  = __ldg(s + p);
    const float y0p = __ldg(y + p);
    const float m   = 1.0f - 2.0f * y0p;     // 1 - dot = fmaf(y0q, m, y0p)  (C=2 softmax)

    const float sH = __ldg(spacing + 0);
    const float sW = __ldg(spacing + 1);
    const float sD = __ldg(spacing + 2);
    // spatial exponent coeffs: -0.5*(spc*delta/5)^2 = -(spc^2/50)*delta^2
    const float aH = sH * sH * (1.0f / 50.0f);
    const float aW = sW * sW * (1.0f / 50.0f);
    const float aD = sD * sD * (1.0f / 50.0f);

    float acc = 0.0f;

    // Half-space offsets (73 of 146 non-center taps); each in-bounds pair
    // counted once and doubled (kernel and (1-dot) are p<->q symmetric).
    #pragma unroll
    for (int dz = 0; dz <= 1; ++dz) {
        #pragma unroll
        for (int dw = -3; dw <= 3; ++dw) {
            #pragma unroll
            for (int dh = -3; dh <= 3; ++dh) {
                if (dz == 0 && (dw < 0 || (dw == 0 && dh <= 0))) continue;
                const int hh = h + dh;
                const int ww = w + dw;
                const int zz = d + dz;
                if (((unsigned)hh < NH) & ((unsigned)ww < NW) & ((unsigned)zz < ND)) {
                    const int q = p + dh * (NW * ND) + dw * ND + dz;
                    const float sq  = __ldg(s + q);
                    const float y0q = __ldg(y + q);
                    const float ds   = sp - sq;
                    const float coff = -(aH * (float)(dh * dh)
                                       + aW * (float)(dw * dw)
                                       + aD * (float)(dz * dz));
                    // image exponent: -0.5*(ds/0.1)^2 = -50*ds^2
                    const float expo = fmaf(-50.0f * ds, ds, coff);
                    const float k = __expf(expo);
                    const float t = fmaf(y0q, m, y0p);
                    acc = fmaf(k, t, acc);
                }
            }
        }
    }
    acc *= 2.0f;

    // OOB taps of the zero-padded unfold: patch value 0 => y-term 0, and
    // k_oob(p) = exp(-0.5*||f(p)||^2), identical for every OOB offset.
    const int cntH = min(h, 3) + min(NH - 1 - h, 3) + 1;
    const int cntW = min(w, 3) + min(NW - 1 - w, 3) + 1;
    const int cntD = min(d, 1) + min(ND - 1 - d, 1) + 1;
    const int noob = 147 - cntH * cntW * cntD;
    if (noob) {
        const float e = -(aH * (float)(h * h) + aW * (float)(w * w) + aD * (float)(d * d))
                        - 50.0f * sp * sp;
        acc = fmaf((float)noob, __expf(e), acc);
    }

    // ---- block reduction: warp shuffle -> shared -> thread 0 ----
    #pragma unroll
    for (int o = 16; o; o >>= 1) acc += __shfl_down_sync(0xffffffffu, acc, o);
    __shared__ float warp_s[8];
    const int lane = threadIdx.x & 31;
    const int wid  = threadIdx.x >> 5;
    if (lane == 0) warp_s[wid] = acc;
    __syncthreads();
    float blk = 0.0f;
    if (wid == 0) {
        blk = (lane < 8) ? warp_s[lane] : 0.0f;
        #pragma unroll
        for (int o = 4; o; o >>= 1) blk += __shfl_down_sync(0xffffffffu, blk, o);
        if (lane == 0) g_part[blockIdx.x] = blk;
    }

    // ---- last-block final reduction (threadFenceReduction pattern) ----
    __threadfence();
    __shared__ bool is_last;
    if (threadIdx.x == 0)
        is_last = (atomicAdd(&g_cnt, 1u) == NBLK - 1);
    __syncthreads();

    if (is_last) {
        float v = g_part[threadIdx.x] + g_part[threadIdx.x + 256];
        #pragma unroll
        for (int o = 16; o; o >>= 1) v += __shfl_down_sync(0xffffffffu, v, o);
        if (lane == 0) warp_s[wid] = v;
        __syncthreads();
        if (wid == 0) {
            float t = (lane < 8) ? warp_s[lane] : 0.0f;
            #pragma unroll
            for (int o = 4; o; o >>= 1) t += __shfl_down_sync(0xffffffffu, t, o);
            if (lane == 0) {
                out[0] = t * (1.0f / (float)NL);
                g_cnt = 0;                 // restore state for next graph replay
            }
        }
    }
}

extern "C" void kernel_launch(void* const* d_in, const int* in_sizes, int n_in,
                              void* d_out, int out_size) {
    const float* y       = (const float*)d_in[0];  // (1,2,64,64,32) softmax; channel 0 used
    const float* sample  = (const float*)d_in[1];  // (1,1,64,64,32)
    const float* spacing = (const float*)d_in[2];  // (3,1)
    k_all<<<NBLK, 256>>>(y, sample, spacing, (float*)d_out);
}

// round 4
// speedup vs baseline: 1.5724x; 1.5724x over previous
#include <cuda_runtime.h>
#include <cuda_bf16.h>

// N=1, C=2, H=64, W=64, D=32, radius=(3,3,1), SIGMA_XY=5, SIGMA_IMG=0.1, WEIGHT=1
#define NH 64
#define NW 64
#define ND 32
#define NL (NH * NW * ND)      // 131072

// Padded scratch: (70, 70, 34), halo = sentinel (s huge -> exp contribution 0)
#define PH 70
#define PW 70
#define PD 34
#define PSTRH (PW * PD)        // 2380
#define PSIZE (PH * PW * PD)   // 166600
#define SENTINEL 1e19f

#define TPB  128
#define NBLK (NL / TPB)        // 1024 main blocks

#define LOG2E 1.4426950408889634f

__device__ float2   g_sy[PSIZE];
__device__ float    g_part[NBLK];
__device__ unsigned g_cnt = 0;   // last main block resets to 0 (graph-replay safe)

// Guaranteed MUFU EX2 regardless of compile flags.
__device__ __forceinline__ float ex2(float x) {
    float r;
    asm("ex2.approx.f32 %0, %1;" : "=f"(r) : "f"(x));
    return r;
}

__global__ __launch_bounds__(TPB) void k_pack(const float* __restrict__ y,
                                              const float* __restrict__ s) {
    const int i = blockIdx.x * TPB + threadIdx.x;
    if (i >= PSIZE) return;
    const int ph = i / PSTRH;
    const int r  = i - ph * PSTRH;
    const int pw = r / PD;
    const int pd = r - pw * PD;
    float2 v = make_float2(SENTINEL, 0.0f);
    if (ph >= 3 && ph < 67 && pw >= 3 && pw < 67 && pd >= 1 && pd < 33) {
        const int p = ((ph - 3) * NW + (pw - 3)) * ND + (pd - 1);
        v = make_float2(s[p], y[p]);
    }
    g_sy[i] = v;
}

__global__ __launch_bounds__(TPB) void k_main(const float* __restrict__ spacing,
                                              float* __restrict__ out) {
    const int p = blockIdx.x * TPB + threadIdx.x;
    const int d = p & (ND - 1);
    const int w = (p >> 5) & (NW - 1);
    const int h = p >> 11;
    const int pp = ((h + 3) * PW + (w + 3)) * PD + (d + 1);

    const float2 c0 = g_sy[pp];
    const float sp  = c0.x;
    const float y0p = c0.y;
    const float m   = 1.0f - 2.0f * y0p;   // 1 - dot = fmaf(y0q, m, y0p)  (C=2 softmax)

    const float sH = __ldg(spacing + 0);
    const float sW = __ldg(spacing + 1);
    const float sD = __ldg(spacing + 2);
    // log2-domain coeffs: exponent2 = -(aH*dh^2 + aW*dw^2 + aD*dz^2) + c2*ds^2
    const float aH = sH * sH * (LOG2E / 50.0f);
    const float aW = sW * sW * (LOG2E / 50.0f);
    const float aD = sD * sD * (LOG2E / 50.0f);
    const float c2 = -50.0f * LOG2E;

    float acc = 0.0f;

    // Half-space offsets (73 of 146 non-center taps); each in-bounds pair
    // counted once and doubled (kernel and (1-dot) are p<->q symmetric).
    // Halo sentinel drives ex2 -> exactly 0, so no bounds checks at all.
    #pragma unroll
    for (int dz = 0; dz <= 1; ++dz) {
        #pragma unroll
        for (int dw = -3; dw <= 3; ++dw) {
            #pragma unroll
            for (int dh = -3; dh <= 3; ++dh) {
                if (dz == 0 && (dw < 0 || (dw == 0 && dh <= 0))) continue;
                const float2 cq = g_sy[pp + dh * PSTRH + dw * PD + dz];
                const float coff = -(aH * (float)(dh * dh)
                                   + aW * (float)(dw * dw)
                                   + aD * (float)(dz * dz));   // CSE'd: 32 distinct values
                const float ds = sp - cq.x;
                const float e2 = fmaf(c2 * ds, ds, coff);
                const float k  = ex2(e2);
                const float t  = fmaf(cq.y, m, y0p);
                acc = fmaf(k, t, acc);
            }
        }
    }
    acc *= 2.0f;

    // OOB taps (zero-padded unfold): y-term 0; kernel value identical per
    // OOB offset: exp(-0.5*||f(p)||^2). Count analytically.
    const int cntH = min(h, 3) + min(NH - 1 - h, 3) + 1;
    const int cntW = min(w, 3) + min(NW - 1 - w, 3) + 1;
    const int cntD = min(d, 1) + min(ND - 1 - d, 1) + 1;
    const int noob = 147 - cntH * cntW * cntD;
    if (noob) {
        const float e = -(aH * (float)(h * h) + aW * (float)(w * w) + aD * (float)(d * d))
                        + c2 * sp * sp;
        acc = fmaf((float)noob, ex2(e), acc);
    }

    // ---- block reduction: warp shuffle -> shared ----
    #pragma unroll
    for (int o = 16; o; o >>= 1) acc += __shfl_down_sync(0xffffffffu, acc, o);
    __shared__ float warp_s[4];
    const int lane = threadIdx.x & 31;
    const int wid  = threadIdx.x >> 5;
    if (lane == 0) warp_s[wid] = acc;
    __syncthreads();
    if (threadIdx.x == 0) {
        g_part[blockIdx.x] = warp_s[0] + warp_s[1] + warp_s[2] + warp_s[3];
    }

    // ---- last-block final reduction ----
    __threadfence();
    __shared__ bool is_last;
    if (threadIdx.x == 0)
        is_last = (atomicAdd(&g_cnt, 1u) == NBLK - 1);
    __syncthreads();

    if (is_last) {
        float v = 0.0f;
        #pragma unroll
        for (int j = 0; j < NBLK / TPB; ++j)
            v += g_part[threadIdx.x + j * TPB];
        #pragma unroll
        for (int o = 16; o; o >>= 1) v += __shfl_down_sync(0xffffffffu, v, o);
        if (lane == 0) warp_s[wid] = v;
        __syncthreads();
        if (threadIdx.x == 0) {
            out[0] = (warp_s[0] + warp_s[1] + warp_s[2] + warp_s[3]) * (1.0f / (float)NL);
            g_cnt = 0;                 // restore for next graph replay
        }
    }
}

extern "C" void kernel_launch(void* const* d_in, const int* in_sizes, int n_in,
                              void* d_out, int out_size) {
    const float* y       = (const float*)d_in[0];  // (1,2,64,64,32) softmax; channel 0 used
    const float* sample  = (const float*)d_in[1];  // (1,1,64,64,32)
    const float* spacing = (const float*)d_in[2];  // (3,1)
    k_pack<<<(PSIZE + TPB - 1) / TPB, TPB>>>(y, sample);
    k_main<<<NBLK, TPB>>>(spacing, (float*)d_out);
}

// round 5
// speedup vs baseline: 1.7843x; 1.1348x over previous
#include <cuda_runtime.h>
#include <cuda_bf16.h>

// N=1, C=2, H=64, W=64, D=32, radius=(3,3,1), SIGMA_XY=5, SIGMA_IMG=0.1, WEIGHT=1
#define NH 64
#define NW 64
#define ND 32
#define NL (NH * NW * ND)      // 131072

#define TPB  128
#define NBLK (NL / TPB)        // 1024 blocks; block = (h=1, w=4, d=32) slab

// smem tile: h 7 x w 10 x d 34 halo'd neighborhood, packed (s, y0)
#define TH 7
#define TW 10
#define TD 34
#define TSTRW TD               // 34
#define TSTRH (TW * TD)        // 340
#define TSIZE (TH * TW * TD)   // 2380

#define SENTINEL 1e19f
#define LOG2E 1.4426950408889634f

__device__ float    g_part[NBLK];
__device__ unsigned g_cnt = 0;   // last block resets to 0 (graph-replay safe)

__device__ __forceinline__ float ex2(float x) {   // guaranteed MUFU EX2
    float r;
    asm("ex2.approx.f32 %0, %1;" : "=f"(r) : "f"(x));
    return r;
}

__global__ __launch_bounds__(TPB) void k_all(const float* __restrict__ y,
                                             const float* __restrict__ s,
                                             const float* __restrict__ spacing,
                                             float* __restrict__ out) {
    __shared__ float2 tile[TSIZE];
    __shared__ float  warp_s[4];

    // block -> slab origin
    const int hbase = blockIdx.x >> 4;          // 0..63
    const int wbase = (blockIdx.x & 15) << 2;   // 0,4,...,60

    // ---- cooperative tile load: global (with sentinel halo) -> smem ----
    #pragma unroll
    for (int i = threadIdx.x; i < TSIZE; i += TPB) {
        const int th = i / TSTRH;
        const int r  = i - th * TSTRH;
        const int tw = r / TD;
        const int td = r - tw * TD;
        const int gh = hbase + th - 3;
        const int gw = wbase + tw - 3;
        const int gd = td - 1;
        float2 v = make_float2(SENTINEL, 0.0f);
        if (((unsigned)gh < NH) & ((unsigned)gw < NW) & ((unsigned)gd < ND)) {
            const int gidx = (gh * NW + gw) * ND + gd;
            v = make_float2(__ldg(s + gidx), __ldg(y + gidx));
        }
        tile[i] = v;
    }
    __syncthreads();

    // thread -> voxel
    const int d  = threadIdx.x & 31;
    const int wl = threadIdx.x >> 5;            // 0..3
    const int w  = wbase + wl;
    const int h  = hbase;
    const int tb = 3 * TSTRH + (wl + 3) * TSTRW + (d + 1);  // center in tile

    const float2 c0 = tile[tb];
    const float sp  = c0.x;
    const float y0p = c0.y;
    const float m   = 1.0f - 2.0f * y0p;        // 1 - dot = fmaf(y0q, m, y0p)  (C=2)

    const float sH = __ldg(spacing + 0);
    const float sW = __ldg(spacing + 1);
    const float sD = __ldg(spacing + 2);
    const float aH = sH * sH * (LOG2E / 50.0f);
    const float aW = sW * sW * (LOG2E / 50.0f);
    const float aD = sD * sD * (LOG2E / 50.0f);
    const float c2 = -50.0f * LOG2E;

    float acc0 = 0.0f, acc1 = 0.0f, acc2 = 0.0f, acc3 = 0.0f;
    int tap = 0;

    // Half-space offsets (73 of 146 non-center taps); each in-bounds pair
    // counted once, doubled below (k and (1-dot) are p<->q symmetric).
    // Sentinel halo drives ex2 -> exactly 0: branch-free, immediate-offset LDS.
    #pragma unroll
    for (int dz = 0; dz <= 1; ++dz) {
        #pragma unroll
        for (int dw = -3; dw <= 3; ++dw) {
            #pragma unroll
            for (int dh = -3; dh <= 3; ++dh) {
                if (dz == 0 && (dw < 0 || (dw == 0 && dh <= 0))) continue;
                const float2 cq = tile[tb + dh * TSTRH + dw * TSTRW + dz];
                const float coff = -(aH * (float)(dh * dh)
                                   + aW * (float)(dw * dw)
                                   + aD * (float)(dz * dz));   // CSE'd constants
                const float t  = fmaf(cq.y, m, y0p);
                const float ds = sp - cq.x;
                const float e2 = fmaf(c2 * ds, ds, coff);
                const float k  = ex2(e2);
                switch (tap & 3) {
                    case 0: acc0 = fmaf(k, t, acc0); break;
                    case 1: acc1 = fmaf(k, t, acc1); break;
                    case 2: acc2 = fmaf(k, t, acc2); break;
                    default: acc3 = fmaf(k, t, acc3); break;
                }
                ++tap;
            }
        }
    }
    float acc = 2.0f * ((acc0 + acc1) + (acc2 + acc3));

    // OOB taps (zero-padded unfold): y-term 0; kernel value identical per
    // OOB offset: exp(-0.5*||f(p)||^2). Count analytically.
    const int cntH = min(h, 3) + min(NH - 1 - h, 3) + 1;
    const int cntW = min(w, 3) + min(NW - 1 - w, 3) + 1;
    const int cntD = min(d, 1) + min(ND - 1 - d, 1) + 1;
    const int noob = 147 - cntH * cntW * cntD;
    if (noob) {
        const float e = -(aH * (float)(h * h) + aW * (float)(w * w) + aD * (float)(d * d))
                        + c2 * sp * sp;
        acc = fmaf((float)noob, ex2(e), acc);
    }

    // ---- block reduction ----
    #pragma unroll
    for (int o = 16; o; o >>= 1) acc += __shfl_down_sync(0xffffffffu, acc, o);
    const int lane = threadIdx.x & 31;
    const int wid  = threadIdx.x >> 5;
    if (lane == 0) warp_s[wid] = acc;
    __syncthreads();
    if (threadIdx.x == 0)
        g_part[blockIdx.x] = (warp_s[0] + warp_s[1]) + (warp_s[2] + warp_s[3]);

    // ---- last-block final reduction ----
    __threadfence();
    __shared__ bool is_last;
    if (threadIdx.x == 0)
        is_last = (atomicAdd(&g_cnt, 1u) == NBLK - 1);
    __syncthreads();

    if (is_last) {
        float v = 0.0f;
        #pragma unroll
        for (int j = 0; j < NBLK / TPB; ++j)
            v += g_part[threadIdx.x + j * TPB];
        #pragma unroll
        for (int o = 16; o; o >>= 1) v += __shfl_down_sync(0xffffffffu, v, o);
        if (lane == 0) warp_s[wid] = v;
        __syncthreads();
        if (threadIdx.x == 0) {
            out[0] = ((warp_s[0] + warp_s[1]) + (warp_s[2] + warp_s[3])) * (1.0f / (float)NL);
            g_cnt = 0;                 // restore for next graph replay
        }
    }
}

extern "C" void kernel_launch(void* const* d_in, const int* in_sizes, int n_in,
                              void* d_out, int out_size) {
    const float* y       = (const float*)d_in[0];  // (1,2,64,64,32) softmax; ch 0 used
    const float* sample  = (const float*)d_in[1];  // (1,1,64,64,32)
    const float* spacing = (const float*)d_in[2];  // (3,1)
    k_all<<<NBLK, TPB>>>(y, sample, spacing, (float*)d_out);
}